// round 12
// baseline (speedup 1.0000x reference)
#include <cuda_runtime.h>
#include <math.h>

// Problem constants
constexpr int S = 4;
constexpr int V = 2;
constexpr int B = 8192;
constexpr int D = 512;
constexpr int KV = S * V;          // 8 vectors per batch element
constexpr int NPAIR = KV * (KV + 1) / 2;  // 36 upper-triangle slots (6 unused)
constexpr float TEMP_INV = 10.0f;  // 1 / 0.1

constexpr int WARPS_PER_BLOCK = 4;
constexpr int THREADS = WARPS_PER_BLOCK * 32;
constexpr int NBLOCKS = B / WARPS_PER_BLOCK;  // 2048

// Deterministic two-stage reduction scratch (allocation-free)
__device__ float g_partials[NBLOCKS];

__host__ __device__ constexpr int TRI(int p, int q) {
    return p * KV + q - p * (p + 1) / 2;  // upper-triangle index, p <= q
}

// The loss never reads odd-odd off-diagonal dots (anchors are v=0 only):
// skip those 6 pairs; their acc slots are dead-coded. 30 live pairs.
__host__ __device__ constexpr bool pair_used(int p, int q) {
    return !((p & 1) && (q & 1) && (p != q));
}

__global__ void __launch_bounds__(THREADS)
gram_loss_kernel(const float* __restrict__ views) {
    const int warp = threadIdx.x >> 5;
    const int lane = threadIdx.x & 31;
    const int b = blockIdx.x * WARPS_PER_BLOCK + warp;

    const float4* base[KV];
#pragma unroll
    for (int k = 0; k < KV; k++)
        base[k] = reinterpret_cast<const float4*>(views + ((size_t)k * B + b) * (size_t)D);

    float acc[NPAIR];
#pragma unroll
    for (int i = 0; i < NPAIR; i++) acc[i] = 0.0f;

    // D=512 floats = 128 float4/vector; 32 lanes -> 4 chunks, coalesced.
    // Register double-buffer: prefetch chunk c+1 while computing chunk c,
    // so DRAM latency overlaps the 120-FMA compute block instead of
    // serializing at each chunk boundary.
    float4 v[KV], vn[KV];
#pragma unroll
    for (int k = 0; k < KV; k++)
        v[k] = __ldg(&base[k][lane]);

#pragma unroll
    for (int c = 0; c < 4; c++) {
        if (c < 3) {
#pragma unroll
            for (int k = 0; k < KV; k++)
                vn[k] = __ldg(&base[k][(c + 1) * 32 + lane]);
        }
#pragma unroll
        for (int p = 0; p < KV; p++) {
#pragma unroll
            for (int q = p; q < KV; q++) {
                if (!pair_used(p, q)) continue;
                float s = acc[TRI(p, q)];
                s = fmaf(v[p].x, v[q].x, s);
                s = fmaf(v[p].y, v[q].y, s);
                s = fmaf(v[p].z, v[q].z, s);
                s = fmaf(v[p].w, v[q].w, s);
                acc[TRI(p, q)] = s;
            }
        }
        if (c < 3) {
#pragma unroll
            for (int k = 0; k < KV; k++)
                v[k] = vn[k];  // register rename, no real moves after unroll
        }
    }

    // Warp butterfly reduce the live partials
#pragma unroll
    for (int off = 16; off >= 1; off >>= 1) {
#pragma unroll
        for (int p = 0; p < KV; p++)
#pragma unroll
            for (int q = p; q < KV; q++)
                if (pair_used(p, q))
                    acc[TRI(p, q)] += __shfl_xor_sync(0xffffffffu, acc[TRI(p, q)], off);
    }

    __shared__ float warp_loss[WARPS_PER_BLOCK];

    if (lane == 0) {
        float invn[KV];
#pragma unroll
        for (int k = 0; k < KV; k++)
            invn[k] = 1.0f / fmaxf(sqrtf(acc[TRI(k, k)]), 1e-12f);

        float loss = 0.0f;
#pragma unroll
        for (int i = 0; i < S; i++) {
            const int a = i * 2;  // anchor = (s=i, v=0)
            float l[7];
            int cnt = 0;
            l[cnt++] = acc[TRI(a, a + 1)] * invn[a] * invn[a + 1] * TEMP_INV;
#pragma unroll
            for (int j = 0; j < S; j++) {
                if (j == i) continue;
#pragma unroll
                for (int v2 = 0; v2 < V; v2++) {
                    const int jk = j * 2 + v2;
                    const int p = a < jk ? a : jk;
                    const int q = a < jk ? jk : a;
                    l[cnt++] = acc[TRI(p, q)] * invn[a] * invn[jk] * TEMP_INV;
                }
            }
            float m = l[0];
#pragma unroll
            for (int t = 1; t < 7; t++) m = fmaxf(m, l[t]);
            float se = 0.0f;
#pragma unroll
            for (int t = 0; t < 7; t++) se += __expf(l[t] - m);
            loss += m + __logf(se) - l[0];
        }
        warp_loss[warp] = loss;
    }
    __syncthreads();

    if (threadIdx.x == 0) {
        float s = 0.0f;
#pragma unroll
        for (int w = 0; w < WARPS_PER_BLOCK; w++) s += warp_loss[w];
        g_partials[blockIdx.x] = s;
    }
    // PDL: this block's contribution is done.
    cudaTriggerProgrammaticLaunchCompletion();
}

// Slim tail, launched via PDL so it overlaps the gram kernel's tail wave.
__global__ void __launch_bounds__(1024)
final_reduce_kernel(float* __restrict__ out) {
    cudaGridDependencySynchronize();

    const int tid = threadIdx.x;
    const int warp = tid >> 5;
    const int lane = tid & 31;

    // NBLOCKS == 2048 == 2 * blockDim.x
    float s = g_partials[tid] + g_partials[tid + 1024];
#pragma unroll
    for (int off = 16; off >= 1; off >>= 1)
        s += __shfl_xor_sync(0xffffffffu, s, off);

    __shared__ float wsum[32];
    if (lane == 0) wsum[warp] = s;
    __syncthreads();

    if (warp == 0) {
        float t = wsum[lane];
#pragma unroll
        for (int off = 16; off >= 1; off >>= 1)
            t += __shfl_xor_sync(0xffffffffu, t, off);
        if (lane == 0) out[0] = t / (float)(S * B);
    }
}

extern "C" void kernel_launch(void* const* d_in, const int* in_sizes, int n_in,
                              void* d_out, int out_size) {
    const float* views = (const float*)d_in[0];
    float* out = (float*)d_out;

    gram_loss_kernel<<<NBLOCKS, THREADS>>>(views);

    cudaLaunchConfig_t cfg = {};
    cfg.gridDim = dim3(1, 1, 1);
    cfg.blockDim = dim3(1024, 1, 1);
    cfg.dynamicSmemBytes = 0;
    cfg.stream = 0;
    cudaLaunchAttribute attrs[1];
    attrs[0].id = cudaLaunchAttributeProgrammaticStreamSerialization;
    attrs[0].val.programmaticStreamSerializationAllowed = 1;
    cfg.attrs = attrs;
    cfg.numAttrs = 1;
    cudaLaunchKernelEx(&cfg, final_reduce_kernel, out);
}

// round 13
// speedup vs baseline: 1.0693x; 1.0693x over previous
#include <cuda_runtime.h>
#include <math.h>

// Problem constants
constexpr int S = 4;
constexpr int V = 2;
constexpr int B = 8192;
constexpr int D = 512;
constexpr int KV = S * V;          // 8 vectors per batch element
constexpr int NPAIR = KV * (KV + 1) / 2;  // 36 upper-triangle slots (6 unused)
constexpr float TEMP_INV = 10.0f;  // 1 / 0.1

constexpr int WARPS_PER_BLOCK = 4;
constexpr int THREADS = WARPS_PER_BLOCK * 32;
constexpr int NBLOCKS = B / WARPS_PER_BLOCK;  // 2048

// Deterministic two-stage reduction scratch (allocation-free)
__device__ float g_partials[NBLOCKS];

__host__ __device__ constexpr int TRI(int p, int q) {
    return p * KV + q - p * (p + 1) / 2;  // upper-triangle index, p <= q
}

// The loss never reads odd-odd off-diagonal dots (anchors are v=0 only):
// skip those 6 pairs; their acc slots are dead-coded. 30 live pairs.
__host__ __device__ constexpr bool pair_used(int p, int q) {
    return !((p & 1) && (q & 1) && (p != q));
}

__global__ void __launch_bounds__(THREADS)
gram_loss_kernel(const float* __restrict__ views) {
    const int warp = threadIdx.x >> 5;
    const int lane = threadIdx.x & 31;
    const int b = blockIdx.x * WARPS_PER_BLOCK + warp;

    const float4* base[KV];
#pragma unroll
    for (int k = 0; k < KV; k++)
        base[k] = reinterpret_cast<const float4*>(views + ((size_t)k * B + b) * (size_t)D);

    float acc[NPAIR];
#pragma unroll
    for (int i = 0; i < NPAIR; i++) acc[i] = 0.0f;

    // D=512 floats = 128 float4/vector; 32 lanes -> 4 chunks, coalesced.
    // Simple per-chunk loads (R11's proven-clean compile); the register
    // double-buffer variant cost ~7us via occupancy loss (R12).
#pragma unroll
    for (int c = 0; c < 4; c++) {
        float4 v[KV];
#pragma unroll
        for (int k = 0; k < KV; k++)
            v[k] = __ldg(&base[k][c * 32 + lane]);
#pragma unroll
        for (int p = 0; p < KV; p++) {
#pragma unroll
            for (int q = p; q < KV; q++) {
                if (!pair_used(p, q)) continue;
                float s = acc[TRI(p, q)];
                s = fmaf(v[p].x, v[q].x, s);
                s = fmaf(v[p].y, v[q].y, s);
                s = fmaf(v[p].z, v[q].z, s);
                s = fmaf(v[p].w, v[q].w, s);
                acc[TRI(p, q)] = s;
            }
        }
    }

    // Warp butterfly reduce the live partials
#pragma unroll
    for (int off = 16; off >= 1; off >>= 1) {
#pragma unroll
        for (int p = 0; p < KV; p++)
#pragma unroll
            for (int q = p; q < KV; q++)
                if (pair_used(p, q))
                    acc[TRI(p, q)] += __shfl_xor_sync(0xffffffffu, acc[TRI(p, q)], off);
    }

    __shared__ float warp_loss[WARPS_PER_BLOCK];

    if (lane == 0) {
        float invn[KV];
#pragma unroll
        for (int k = 0; k < KV; k++)
            invn[k] = 1.0f / fmaxf(sqrtf(acc[TRI(k, k)]), 1e-12f);

        float loss = 0.0f;
#pragma unroll
        for (int i = 0; i < S; i++) {
            const int a = i * 2;  // anchor = (s=i, v=0)
            float l[7];
            int cnt = 0;
            l[cnt++] = acc[TRI(a, a + 1)] * invn[a] * invn[a + 1] * TEMP_INV;
#pragma unroll
            for (int j = 0; j < S; j++) {
                if (j == i) continue;
#pragma unroll
                for (int v2 = 0; v2 < V; v2++) {
                    const int jk = j * 2 + v2;
                    const int p = a < jk ? a : jk;
                    const int q = a < jk ? jk : a;
                    l[cnt++] = acc[TRI(p, q)] * invn[a] * invn[jk] * TEMP_INV;
                }
            }
            float m = l[0];
#pragma unroll
            for (int t = 1; t < 7; t++) m = fmaxf(m, l[t]);
            float se = 0.0f;
#pragma unroll
            for (int t = 0; t < 7; t++) se += __expf(l[t] - m);
            loss += m + __logf(se) - l[0];
        }
        warp_loss[warp] = loss;
    }
    __syncthreads();

    if (threadIdx.x == 0) {
        float s = 0.0f;
#pragma unroll
        for (int w = 0; w < WARPS_PER_BLOCK; w++) s += warp_loss[w];
        g_partials[blockIdx.x] = s;
    }
    // PDL: this block's contribution is done.
    cudaTriggerProgrammaticLaunchCompletion();
}

// Slim tail, launched via PDL so it overlaps the gram kernel's tail wave.
__global__ void __launch_bounds__(1024)
final_reduce_kernel(float* __restrict__ out) {
    cudaGridDependencySynchronize();

    const int tid = threadIdx.x;
    const int warp = tid >> 5;
    const int lane = tid & 31;

    // NBLOCKS == 2048 == 2 * blockDim.x
    float s = g_partials[tid] + g_partials[tid + 1024];
#pragma unroll
    for (int off = 16; off >= 1; off >>= 1)
        s += __shfl_xor_sync(0xffffffffu, s, off);

    __shared__ float wsum[32];
    if (lane == 0) wsum[warp] = s;
    __syncthreads();

    if (warp == 0) {
        float t = wsum[lane];
#pragma unroll
        for (int off = 16; off >= 1; off >>= 1)
            t += __shfl_xor_sync(0xffffffffu, t, off);
        if (lane == 0) out[0] = t / (float)(S * B);
    }
}

extern "C" void kernel_launch(void* const* d_in, const int* in_sizes, int n_in,
                              void* d_out, int out_size) {
    const float* views = (const float*)d_in[0];
    float* out = (float*)d_out;

    gram_loss_kernel<<<NBLOCKS, THREADS>>>(views);

    cudaLaunchConfig_t cfg = {};
    cfg.gridDim = dim3(1, 1, 1);
    cfg.blockDim = dim3(1024, 1, 1);
    cfg.dynamicSmemBytes = 0;
    cfg.stream = 0;
    cudaLaunchAttribute attrs[1];
    attrs[0].id = cudaLaunchAttributeProgrammaticStreamSerialization;
    attrs[0].val.programmaticStreamSerializationAllowed = 1;
    cfg.attrs = attrs;
    cfg.numAttrs = 1;
    cudaLaunchKernelEx(&cfg, final_reduce_kernel, out);
}

// round 15
// speedup vs baseline: 1.2182x; 1.1393x over previous
#include <cuda_runtime.h>
#include <math.h>
#include <cstdint>

// Problem constants
constexpr int S = 4;
constexpr int V = 2;
constexpr int B = 8192;
constexpr int D = 512;
constexpr int KV = S * V;          // 8 vectors per batch element
constexpr int NPAIR = KV * (KV + 1) / 2;  // 36 upper-triangle slots (6 unused)
constexpr float TEMP_INV = 10.0f;  // 1 / 0.1

constexpr int WARPS_PER_BLOCK = 4;
constexpr int THREADS = WARPS_PER_BLOCK * 32;
constexpr int NBLOCKS = B / WARPS_PER_BLOCK;  // 2048

// Deterministic two-stage reduction scratch (allocation-free)
__device__ float g_partials[NBLOCKS];

__host__ __device__ constexpr int TRI(int p, int q) {
    return p * KV + q - p * (p + 1) / 2;  // upper-triangle index, p <= q
}

// The loss never reads odd-odd off-diagonal dots: skip those 6 pairs.
__host__ __device__ constexpr bool pair_used(int p, int q) {
    return !((p & 1) && (q & 1) && (p != q));
}

__global__ void __launch_bounds__(THREADS)
gram_loss_kernel(const float* __restrict__ views) {
    const int warp = threadIdx.x >> 5;
    const int lane = threadIdx.x & 31;
    const int b = blockIdx.x * WARPS_PER_BLOCK + warp;

    // 2-stage cp.async pipeline buffer. Lane l stages and reads back the SAME
    // 16B slot (sm[st][warp][k][l]) -> per-thread wait_group is the only sync
    // needed (own async writes are visible to the issuing thread after wait).
    __shared__ float4 smbuf[2][WARPS_PER_BLOCK][KV][32];

    const float4* gbase[KV];
#pragma unroll
    for (int k = 0; k < KV; k++)
        gbase[k] = reinterpret_cast<const float4*>(
            views + ((size_t)k * B + b) * (size_t)D);

    float acc[NPAIR];
#pragma unroll
    for (int i = 0; i < NPAIR; i++) acc[i] = 0.0f;

    // Stage chunk 0
#pragma unroll
    for (int k = 0; k < KV; k++) {
        unsigned int dst =
            (unsigned int)__cvta_generic_to_shared(&smbuf[0][warp][k][lane]);
        asm volatile("cp.async.cg.shared.global [%0], [%1], 16;"
                     :: "r"(dst), "l"(gbase[k] + lane));
    }
    asm volatile("cp.async.commit_group;" ::: "memory");

    // D=512 floats = 128 float4/vector; 4 chunks of 32 float4 per lane.
    // While computing chunk c, chunk c+1 streams into the other stage.
#pragma unroll
    for (int c = 0; c < 4; c++) {
        const int st = c & 1;
        if (c < 3) {
#pragma unroll
            for (int k = 0; k < KV; k++) {
                unsigned int dst = (unsigned int)__cvta_generic_to_shared(
                    &smbuf[st ^ 1][warp][k][lane]);
                asm volatile("cp.async.cg.shared.global [%0], [%1], 16;"
                             :: "r"(dst), "l"(gbase[k] + (c + 1) * 32 + lane));
            }
            asm volatile("cp.async.commit_group;" ::: "memory");
            asm volatile("cp.async.wait_group 1;" ::: "memory");  // chunk c ready
        } else {
            asm volatile("cp.async.wait_group 0;" ::: "memory");
        }

        float4 v[KV];
#pragma unroll
        for (int k = 0; k < KV; k++)
            v[k] = smbuf[st][warp][k][lane];
#pragma unroll
        for (int p = 0; p < KV; p++) {
#pragma unroll
            for (int q = p; q < KV; q++) {
                if (!pair_used(p, q)) continue;
                float s = acc[TRI(p, q)];
                s = fmaf(v[p].x, v[q].x, s);
                s = fmaf(v[p].y, v[q].y, s);
                s = fmaf(v[p].z, v[q].z, s);
                s = fmaf(v[p].w, v[q].w, s);
                acc[TRI(p, q)] = s;
            }
        }
    }

    // Warp butterfly reduce the live partials
#pragma unroll
    for (int off = 16; off >= 1; off >>= 1) {
#pragma unroll
        for (int p = 0; p < KV; p++)
#pragma unroll
            for (int q = p; q < KV; q++)
                if (pair_used(p, q))
                    acc[TRI(p, q)] += __shfl_xor_sync(0xffffffffu, acc[TRI(p, q)], off);
    }

    __shared__ float warp_loss[WARPS_PER_BLOCK];

    if (lane == 0) {
        float invn[KV];
#pragma unroll
        for (int k = 0; k < KV; k++)
            invn[k] = 1.0f / fmaxf(sqrtf(acc[TRI(k, k)]), 1e-12f);

        float loss = 0.0f;
#pragma unroll
        for (int i = 0; i < S; i++) {
            const int a = i * 2;  // anchor = (s=i, v=0)
            float l[7];
            int cnt = 0;
            l[cnt++] = acc[TRI(a, a + 1)] * invn[a] * invn[a + 1] * TEMP_INV;
#pragma unroll
            for (int j = 0; j < S; j++) {
                if (j == i) continue;
#pragma unroll
                for (int v2 = 0; v2 < V; v2++) {
                    const int jk = j * 2 + v2;
                    const int p = a < jk ? a : jk;
                    const int q = a < jk ? jk : a;
                    l[cnt++] = acc[TRI(p, q)] * invn[a] * invn[jk] * TEMP_INV;
                }
            }
            float m = l[0];
#pragma unroll
            for (int t = 1; t < 7; t++) m = fmaxf(m, l[t]);
            float se = 0.0f;
#pragma unroll
            for (int t = 0; t < 7; t++) se += __expf(l[t] - m);
            loss += m + __logf(se) - l[0];
        }
        warp_loss[warp] = loss;
    }
    __syncthreads();

    if (threadIdx.x == 0) {
        float s = 0.0f;
#pragma unroll
        for (int w = 0; w < WARPS_PER_BLOCK; w++) s += warp_loss[w];
        g_partials[blockIdx.x] = s;
    }
    cudaTriggerProgrammaticLaunchCompletion();
}

// Slim tail, launched via PDL so it overlaps the gram kernel's tail wave.
__global__ void __launch_bounds__(1024)
final_reduce_kernel(float* __restrict__ out) {
    cudaGridDependencySynchronize();

    const int tid = threadIdx.x;
    const int warp = tid >> 5;
    const int lane = tid & 31;

    // NBLOCKS == 2048 == 2 * blockDim.x
    float s = g_partials[tid] + g_partials[tid + 1024];
#pragma unroll
    for (int off = 16; off >= 1; off >>= 1)
        s += __shfl_xor_sync(0xffffffffu, s, off);

    __shared__ float wsum[32];
    if (lane == 0) wsum[warp] = s;
    __syncthreads();

    if (warp == 0) {
        float t = wsum[lane];
#pragma unroll
        for (int off = 16; off >= 1; off >>= 1)
            t += __shfl_xor_sync(0xffffffffu, t, off);
        if (lane == 0) out[0] = t / (float)(S * B);
    }
}

extern "C" void kernel_launch(void* const* d_in, const int* in_sizes, int n_in,
                              void* d_out, int out_size) {
    const float* views = (const float*)d_in[0];
    float* out = (float*)d_out;

    gram_loss_kernel<<<NBLOCKS, THREADS>>>(views);

    cudaLaunchConfig_t cfg = {};
    cfg.gridDim = dim3(1, 1, 1);
    cfg.blockDim = dim3(1024, 1, 1);
    cfg.dynamicSmemBytes = 0;
    cfg.stream = 0;
    cudaLaunchAttribute attrs[1];
    attrs[0].id = cudaLaunchAttributeProgrammaticStreamSerialization;
    attrs[0].val.programmaticStreamSerializationAllowed = 1;
    cfg.attrs = attrs;
    cfg.numAttrs = 1;
    cudaLaunchKernelEx(&cfg, final_reduce_kernel, out);
}